// round 1
// baseline (speedup 1.0000x reference)
#include <cuda_runtime.h>
#include <cuda_bf16.h>
#include <cstdint>

// Problem constants
#define BATCH   64
#define SEQ     1024
#define IDIM    128
#define HDIM    512
#define G4      2048          // 4*HDIM
#define KTOT    640           // HDIM + IDIM  (fused [h, x] @ [U; W])
#define NGRP    4             // independent batch groups
#define GB      16            // batches per group   (M of recurrent GEMM)
#define NCTA    32            // CTAs per group
#define HC      16            // hidden units owned per CTA
#define NL      64            // local gate columns per CTA = 4*HC
#define THREADS 128
#define NKC     (KTOT / 16)   // 40 k-chunks of 16

// smem element strides (bf16 elems), padded so (stride/2) % 32 == 4 -> conflict-free frags
#define ZSTR 648
#define ASTR 648

// smem byte offsets
#define OFF_ZHI   0
#define OFF_ZLO   (OFF_ZHI + NL * ZSTR * 2)          // 82944
#define OFF_AHI   (OFF_ZLO + NL * ZSTR * 2)          // 165888
#define OFF_ALO   (OFF_AHI + GB * ASTR * 2)          // 186624
#define OFF_GATES (OFF_ALO + GB * ASTR * 2)          // 207360
#define OFF_C     (OFF_GATES + 4 * GB * HC * 4)      // 211456
#define OFF_BIAS  (OFF_C + GB * HC * 4)              // 212480
#define SMEM_SZ   (OFF_BIAS + NL * 4)                // 212736 bytes

// Global scratch (allowed: __device__ arrays, no allocation)
__device__ float g_h[2][BATCH][HDIM];   // ping-pong hidden state
__device__ int   g_cnt[NGRP];
__device__ int   g_gen[NGRP];

// -------- group barrier (sense-reversing, replay-safe: cnt returns to 0) ------
__device__ __forceinline__ int bar_sync(int grp, int my)
{
    __threadfence();
    if (atomicAdd(&g_cnt[grp], 1) == NCTA - 1) {
        atomicExch(&g_cnt[grp], 0);
        __threadfence();
        atomicAdd(&g_gen[grp], 1);
        __threadfence();
        return my + 1;
    }
    int v;
    do {
        asm volatile("ld.acquire.gpu.global.b32 %0, [%1];"
                     : "=r"(v) : "l"(&g_gen[grp]));
    } while (v == my);
    return v;
}

// -------- bf16 MMA m16n8k16 (f32 accum) --------------------------------------
__device__ __forceinline__ void mma_bf16(float* d, const unsigned* a, const unsigned* b)
{
    asm volatile(
        "mma.sync.aligned.m16n8k16.row.col.f32.bf16.bf16.f32 "
        "{%0,%1,%2,%3}, {%4,%5,%6,%7}, {%8,%9}, {%0,%1,%2,%3};\n"
        : "+f"(d[0]), "+f"(d[1]), "+f"(d[2]), "+f"(d[3])
        : "r"(a[0]), "r"(a[1]), "r"(a[2]), "r"(a[3]), "r"(b[0]), "r"(b[1]));
}

__device__ __forceinline__ float fast_sigmoid(float x) { return 1.f / (1.f + __expf(-x)); }
__device__ __forceinline__ float fast_tanh(float x)    { return 1.f - 2.f / (__expf(2.f * x) + 1.f); }

// ==============================================================================
// Persistent recurrent kernel: 4 groups x 32 CTAs, weights SMEM-resident,
// bf16 hi/lo 3-pass tensor-core GEMM per step, fp32 state.
// ==============================================================================
extern "C" __global__ void __launch_bounds__(THREADS, 1)
lstm_persistent_kernel(const float* __restrict__ x,
                       const float* __restrict__ W,
                       const float* __restrict__ U,
                       const float* __restrict__ bias)
{
    extern __shared__ char smem[];
    __nv_bfloat16* zhi  = (__nv_bfloat16*)(smem + OFF_ZHI);
    __nv_bfloat16* zlo  = (__nv_bfloat16*)(smem + OFF_ZLO);
    __nv_bfloat16* ahi  = (__nv_bfloat16*)(smem + OFF_AHI);
    __nv_bfloat16* alo  = (__nv_bfloat16*)(smem + OFF_ALO);
    float*         gat  = (float*)(smem + OFF_GATES);   // [4][GB][HC]
    float*         cmem = (float*)(smem + OFF_C);       // [GB][HC]
    float*         bs   = (float*)(smem + OFF_BIAS);    // [NL]

    const int tid  = threadIdx.x;
    const int lane = tid & 31;
    const int warp = tid >> 5;            // warp == gate index (0..3)
    const int grp  = blockIdx.x >> 5;     // 0..3
    const int gc   = blockIdx.x & 31;     // hidden-slice id within group
    const int b0   = grp * GB;            // first batch of this group
    const int h0   = gc * HC;             // first hidden unit owned

    // ---------------- prologue: load Z = [U; W] column slice, split hi/lo ------
    for (int idx = tid; idx < KTOT * NL; idx += THREADS) {
        int k  = idx >> 6;
        int nl = idx & 63;
        int g  = nl >> 4, hid = nl & 15;
        int col = g * HDIM + h0 + hid;
        float v = (k < HDIM) ? U[(size_t)k * G4 + col]
                             : W[(size_t)(k - HDIM) * G4 + col];
        __nv_bfloat16 hi = __float2bfloat16(v);
        float lo = v - __bfloat162float(hi);
        zhi[nl * ZSTR + k] = hi;
        zlo[nl * ZSTR + k] = __float2bfloat16(lo);
    }
    if (tid < NL) {
        int g = tid >> 4, hid = tid & 15;
        bs[tid] = bias[g * HDIM + h0 + hid];
    }
    for (int idx = tid; idx < GB * HC; idx += THREADS) {
        cmem[idx] = 0.f;
        int b = idx >> 4, hid = idx & 15;
        g_h[0][b0 + b][h0 + hid] = 0.f;   // zero initial hidden state slice
    }
    __threadfence();
    __syncthreads();
    int mygen = 0;
    if (tid == 0) {
        asm volatile("ld.acquire.gpu.global.b32 %0, [%1];"
                     : "=r"(mygen) : "l"(&g_gen[grp]));
        mygen = bar_sync(grp, mygen);
    }
    __syncthreads();

    const int r  = lane >> 2;           // fragment row (0..7)
    const int cq = (lane & 3) * 2;      // fragment col pair base

    // ---------------- time loop ------------------------------------------------
    for (int s = 0; s < SEQ; s++) {
        const int par = s & 1;

        // ---- stage A = [h | x_s] as bf16 hi/lo into smem ----
        const float* hsrc = &g_h[par][b0][0];
        for (int idx = tid; idx < GB * HDIM / 2; idx += THREADS) {   // 4096 pairs
            int b = idx >> 8, kp = idx & 255;
            float2 v = *(const float2*)(hsrc + b * HDIM + kp * 2);
            __nv_bfloat162 h2, l2;
            h2.x = __float2bfloat16(v.x);
            h2.y = __float2bfloat16(v.y);
            l2.x = __float2bfloat16(v.x - __bfloat162float(h2.x));
            l2.y = __float2bfloat16(v.y - __bfloat162float(h2.y));
            *(__nv_bfloat162*)(ahi + b * ASTR + kp * 2) = h2;
            *(__nv_bfloat162*)(alo + b * ASTR + kp * 2) = l2;
        }
        for (int idx = tid; idx < GB * IDIM / 2; idx += THREADS) {   // 1024 pairs
            int b = idx >> 6, ip = idx & 63;
            float2 v = *(const float2*)(x + ((size_t)(b0 + b) * SEQ + s) * IDIM + ip * 2);
            __nv_bfloat162 h2, l2;
            h2.x = __float2bfloat16(v.x);
            h2.y = __float2bfloat16(v.y);
            l2.x = __float2bfloat16(v.x - __bfloat162float(h2.x));
            l2.y = __float2bfloat16(v.y - __bfloat162float(h2.y));
            *(__nv_bfloat162*)(ahi + b * ASTR + HDIM + ip * 2) = h2;
            *(__nv_bfloat162*)(alo + b * ASTR + HDIM + ip * 2) = l2;
        }
        __syncthreads();

        // ---- GEMM: gates(16x64) += A(16x640) @ Z(640x64), 3-pass hi/lo ----
        float acc[2][4];
        #pragma unroll
        for (int t = 0; t < 2; t++)
            #pragma unroll
            for (int j = 0; j < 4; j++) acc[t][j] = 0.f;

        #pragma unroll 2
        for (int kc = 0; kc < NKC; kc++) {
            const int k0 = kc * 16;
            unsigned a_h[4], a_l[4];
            a_h[0] = *(const unsigned*)(ahi + r * ASTR + k0 + cq);
            a_h[1] = *(const unsigned*)(ahi + (r + 8) * ASTR + k0 + cq);
            a_h[2] = *(const unsigned*)(ahi + r * ASTR + k0 + cq + 8);
            a_h[3] = *(const unsigned*)(ahi + (r + 8) * ASTR + k0 + cq + 8);
            a_l[0] = *(const unsigned*)(alo + r * ASTR + k0 + cq);
            a_l[1] = *(const unsigned*)(alo + (r + 8) * ASTR + k0 + cq);
            a_l[2] = *(const unsigned*)(alo + r * ASTR + k0 + cq + 8);
            a_l[3] = *(const unsigned*)(alo + (r + 8) * ASTR + k0 + cq + 8);
            #pragma unroll
            for (int t = 0; t < 2; t++) {
                const int n = warp * 16 + t * 8 + r;
                unsigned b_h[2], b_l[2];
                b_h[0] = *(const unsigned*)(zhi + n * ZSTR + k0 + cq);
                b_h[1] = *(const unsigned*)(zhi + n * ZSTR + k0 + 8 + cq);
                b_l[0] = *(const unsigned*)(zlo + n * ZSTR + k0 + cq);
                b_l[1] = *(const unsigned*)(zlo + n * ZSTR + k0 + 8 + cq);
                mma_bf16(acc[t], a_h, b_h);   // hi*hi
                mma_bf16(acc[t], a_l, b_h);   // lo*hi
                mma_bf16(acc[t], a_h, b_l);   // hi*lo
            }
        }

        // ---- write gate accumulators to smem ----
        #pragma unroll
        for (int t = 0; t < 2; t++) {
            const int cb = t * 8 + cq;
            gat[warp * 256 + r * 16 + cb]           = acc[t][0];
            gat[warp * 256 + r * 16 + cb + 1]       = acc[t][1];
            gat[warp * 256 + (r + 8) * 16 + cb]     = acc[t][2];
            gat[warp * 256 + (r + 8) * 16 + cb + 1] = acc[t][3];
        }
        __syncthreads();

        // ---- elementwise LSTM cell update (256 elems over 128 threads) ----
        const int npar = (s + 1) & 1;
        #pragma unroll
        for (int e = 0; e < 2; e++) {
            int idx = tid + e * THREADS;
            int b = idx >> 4, hid = idx & 15;
            float gi = gat[0 * 256 + b * 16 + hid] + bs[0 * 16 + hid];
            float gf = gat[1 * 256 + b * 16 + hid] + bs[1 * 16 + hid];
            float gg = gat[2 * 256 + b * 16 + hid] + bs[2 * 16 + hid];
            float go = gat[3 * 256 + b * 16 + hid] + bs[3 * 16 + hid];
            float i_ = fast_sigmoid(gi);
            float f_ = fast_sigmoid(gf);
            float g_ = fast_tanh(gg);
            float o_ = fast_sigmoid(go);
            float c  = f_ * cmem[idx] + i_ * g_;
            cmem[idx] = c;
            g_h[npar][b0 + b][h0 + hid] = o_ * fast_tanh(c);
        }
        __threadfence();
        __syncthreads();
        if (tid == 0) mygen = bar_sync(grp, mygen);
        __syncthreads();
    }
}

// ==============================================================================
// Final FC head: out[b, o] = h_last[b] . fc_w[:, o] + fc_b[o]
// h_last lives in g_h[SEQ & 1] == g_h[0]
// ==============================================================================
extern "C" __global__ void fc_kernel(const float* __restrict__ fc_w,
                                     const float* __restrict__ fc_b,
                                     float* __restrict__ out)
{
    const int b    = blockIdx.x;
    const int warp = threadIdx.x >> 5;   // output index 0..6
    const int lane = threadIdx.x & 31;
    float acc = 0.f;
    for (int k = lane; k < HDIM; k += 32)
        acc += g_h[0][b][k] * fc_w[k * 7 + warp];
    #pragma unroll
    for (int o = 16; o > 0; o >>= 1)
        acc += __shfl_down_sync(0xffffffffu, acc, o);
    if (lane == 0) out[b * 7 + warp] = acc + fc_b[warp];
}

// ==============================================================================
extern "C" void kernel_launch(void* const* d_in, const int* in_sizes, int n_in,
                              void* d_out, int out_size)
{
    (void)in_sizes; (void)n_in; (void)out_size;
    const float* x    = (const float*)d_in[0];
    const float* W    = (const float*)d_in[1];
    const float* U    = (const float*)d_in[2];
    const float* bias = (const float*)d_in[3];
    const float* fc_w = (const float*)d_in[4];
    const float* fc_b = (const float*)d_in[5];

    cudaFuncSetAttribute(lstm_persistent_kernel,
                         cudaFuncAttributeMaxDynamicSharedMemorySize, SMEM_SZ);
    lstm_persistent_kernel<<<NGRP * NCTA, THREADS, SMEM_SZ>>>(x, W, U, bias);
    fc_kernel<<<BATCH, 224>>>(fc_w, fc_b, (float*)d_out);
}